// round 1
// baseline (speedup 1.0000x reference)
#include <cuda_runtime.h>
#include <math.h>
#include <stdint.h>

// ---------------- problem constants ----------------
#define BB    256     // batch
#define NTOT  175     // N*K + Q
#define NWAY  20
#define KSHOT 5
#define QN    75
#define DD    512
#define LL    4
#define KNEI  5
#define TAUINV 10.0f  // 1/TAU
#define NKQ   (NWAY*KSHOT)   // 100
#define CHUNKS 5
#define ROWS_PER_CHUNK 35

// ---------------- device scratch (no allocations allowed) ----------------
__device__ float g_V   [(size_t)BB*NTOT*DD];
__device__ float g_V0  [(size_t)BB*NTOT*DD];
__device__ float g_msg [(size_t)BB*NTOT*DD];
__device__ float g_gemm[(size_t)BB*NTOT*DD];
__device__ float g_P    [(size_t)BB*NWAY*DD];
__device__ float g_P0   [(size_t)BB*NWAY*DD];
__device__ float g_Pmsg [(size_t)BB*NWAY*DD];
__device__ float g_Pgemm[(size_t)BB*NWAY*DD];
__device__ float g_Pa   [(size_t)BB*NWAY*DD];
__device__ float g_sim [(size_t)BB*NTOT*NTOT];
__device__ float g_simP[(size_t)BB*NWAY*NWAY];
__device__ int   g_idx [(size_t)BB*NTOT*KNEI];
__device__ float g_w   [(size_t)BB*NTOT*KNEI];
__device__ int   g_idxP[(size_t)BB*NWAY*KNEI];
__device__ float g_wP  [(size_t)BB*NWAY*KNEI];
__device__ float g_lossP[BB*CHUNKS];
__device__ int   g_accP [BB*CHUNKS];

// ---------------- helpers ----------------
__device__ __forceinline__ float blockSum(float v, float* red) {
    int tid = threadIdx.x;
    #pragma unroll
    for (int off = 16; off; off >>= 1) v += __shfl_down_sync(0xffffffffu, v, off);
    if ((tid & 31) == 0) red[tid >> 5] = v;
    __syncthreads();
    float r = 0.f;
    int nw = blockDim.x >> 5;
    if (tid < 32) {
        if (tid < nw) r = red[tid];
        #pragma unroll
        for (int off = 16; off; off >>= 1) r += __shfl_down_sync(0xffffffffu, r, off);
        if (tid == 0) red[0] = r;
    }
    __syncthreads();
    r = red[0];
    __syncthreads();
    return r;
}

// ---------------- kernels ----------------

__global__ void k_zero() {
    int i = blockIdx.x * 256 + threadIdx.x;
    if (i < BB * CHUNKS) { g_lossP[i] = 0.f; g_accP[i] = 0; }
}

// l2-normalize rows, write to two destinations (x and its residual anchor x0)
__global__ void k_init(const float* __restrict__ in, float* __restrict__ out,
                       float* __restrict__ out0) {
    __shared__ float red[8];
    size_t row = blockIdx.x;
    int t = threadIdx.x;                    // 128 threads, 512/4 float4
    float4 v = ((const float4*)(in + row * DD))[t];
    float ss = v.x*v.x + v.y*v.y + v.z*v.z + v.w*v.w;
    ss = blockSum(ss, red);
    float inv = 1.f / fmaxf(sqrtf(ss), 1e-12f);
    float4 o = make_float4(v.x*inv, v.y*inv, v.z*inv, v.w*inv);
    ((float4*)(out  + row * DD))[t] = o;
    ((float4*)(out0 + row * DD))[t] = o;
}

// C[m,n] = sum_k A[m,k]*B[n,k]   (A:[M,K] rm, B:[N,K] rm), batched via blockIdx.z
__global__ __launch_bounds__(256) void k_gemm_nt(
    const float* __restrict__ A, const float* __restrict__ Bm, float* __restrict__ C,
    int M, int N, int K, size_t sA, size_t sB, size_t sC)
{
    __shared__ float As[8][128];
    __shared__ float Bs[8][128];
    const float* Ab = A  + (size_t)blockIdx.z * sA;
    const float* Bb = Bm + (size_t)blockIdx.z * sB;
    float*       Cb = C  + (size_t)blockIdx.z * sC;
    int tid = threadIdx.x;
    int m0 = blockIdx.y * 128, n0 = blockIdx.x * 128;
    int lr = tid >> 1;
    int lk = (tid & 1) << 2;
    int ty = tid >> 4, tx = tid & 15;
    float acc[8][8];
    #pragma unroll
    for (int i = 0; i < 8; i++)
        #pragma unroll
        for (int j = 0; j < 8; j++) acc[i][j] = 0.f;
    int ar = m0 + lr, br = n0 + lr;
    bool aok = ar < M, bok = br < N;
    const float* Aptr = Ab + (size_t)ar * K + lk;
    const float* Bptr = Bb + (size_t)br * K + lk;
    for (int k0 = 0; k0 < K; k0 += 8) {
        float4 a4 = aok ? *(const float4*)(Aptr + k0) : make_float4(0,0,0,0);
        float4 b4 = bok ? *(const float4*)(Bptr + k0) : make_float4(0,0,0,0);
        __syncthreads();
        As[lk+0][lr]=a4.x; As[lk+1][lr]=a4.y; As[lk+2][lr]=a4.z; As[lk+3][lr]=a4.w;
        Bs[lk+0][lr]=b4.x; Bs[lk+1][lr]=b4.y; Bs[lk+2][lr]=b4.z; Bs[lk+3][lr]=b4.w;
        __syncthreads();
        #pragma unroll
        for (int k = 0; k < 8; k++) {
            float a[8], b[8];
            *(float4*)(a)   = *(const float4*)&As[k][ty*4];
            *(float4*)(a+4) = *(const float4*)&As[k][64 + ty*4];
            *(float4*)(b)   = *(const float4*)&Bs[k][tx*4];
            *(float4*)(b+4) = *(const float4*)&Bs[k][64 + tx*4];
            #pragma unroll
            for (int i = 0; i < 8; i++)
                #pragma unroll
                for (int j = 0; j < 8; j++)
                    acc[i][j] += a[i] * b[j];
        }
    }
    #pragma unroll
    for (int i = 0; i < 8; i++) {
        int m = m0 + ((i < 4) ? (ty*4 + i) : (64 + ty*4 + i - 4));
        if (m >= M) continue;
        #pragma unroll
        for (int j = 0; j < 8; j++) {
            int n = n0 + ((j < 4) ? (tx*4 + j) : (64 + tx*4 + j - 4));
            if (n < N) Cb[(size_t)m * N + n] = acc[i][j];
        }
    }
}

// per-row top-KNEI + softmax(vals/tau); one warp per row
__global__ void k_topk(const float* __restrict__ sim, int nCols, int totalRows,
                       int* __restrict__ idxOut, float* __restrict__ wOut)
{
    int row = blockIdx.x * 4 + (threadIdx.x >> 5);
    if (row >= totalRows) return;
    int lane = threadIdx.x & 31;
    const float* sr = sim + (size_t)row * nCols;
    float v[6];
    #pragma unroll
    for (int j = 0; j < 6; j++) {
        int c = lane + j * 32;
        v[j] = (c < nCols) ? sr[c] : -INFINITY;
    }
    float cv[KNEI]; int ci[KNEI];
    #pragma unroll
    for (int p = 0; p < KNEI; p++) {
        float bv = -INFINITY; int bc = 0x7fffffff;
        #pragma unroll
        for (int j = 0; j < 6; j++) {
            if (v[j] > bv) { bv = v[j]; bc = lane + j * 32; }
        }
        #pragma unroll
        for (int off = 16; off; off >>= 1) {
            float ov = __shfl_down_sync(0xffffffffu, bv, off);
            int   oc = __shfl_down_sync(0xffffffffu, bc, off);
            if (ov > bv || (ov == bv && oc < bc)) { bv = ov; bc = oc; }
        }
        bv = __shfl_sync(0xffffffffu, bv, 0);
        bc = __shfl_sync(0xffffffffu, bc, 0);
        cv[p] = bv; ci[p] = bc;
        if ((bc & 31) == lane) v[bc >> 5] = -INFINITY;
    }
    if (lane == 0) {
        float mx = cv[0];
        float e[KNEI], s = 0.f;
        #pragma unroll
        for (int p = 0; p < KNEI; p++) { e[p] = expf((cv[p] - mx) * TAUINV); s += e[p]; }
        float inv = 1.f / s;
        #pragma unroll
        for (int p = 0; p < KNEI; p++) {
            idxOut[(size_t)row * KNEI + p] = ci[p];
            wOut [(size_t)row * KNEI + p] = e[p] * inv;
        }
    }
}

// msg[row,:] = sum_p w[p] * src[b, idx[p], :]   (sparse adj @ x)
__global__ void k_gather(const float* __restrict__ src, const int* __restrict__ idx,
                         const float* __restrict__ w, float* __restrict__ msg,
                         int rowsPerB)
{
    int row = blockIdx.x;
    int b = row / rowsPerB;
    const int*   ir = idx + (size_t)row * KNEI;
    const float* wr = w   + (size_t)row * KNEI;
    int   ji[KNEI]; float wj[KNEI];
    #pragma unroll
    for (int p = 0; p < KNEI; p++) { ji[p] = ir[p]; wj[p] = wr[p]; }
    const float* base = src + (size_t)b * rowsPerB * DD;
    int t = threadIdx.x;   // 128
    float4 acc = make_float4(0,0,0,0);
    #pragma unroll
    for (int p = 0; p < KNEI; p++) {
        float4 x = ((const float4*)(base + (size_t)ji[p] * DD))[t];
        acc.x += wj[p]*x.x; acc.y += wj[p]*x.y; acc.z += wj[p]*x.z; acc.w += wj[p]*x.w;
    }
    ((float4*)(msg + (size_t)row * DD))[t] = acc;
}

// x = l2n(0.8*(x + s*tanh(G + bias)) + 0.2*x0)
__global__ void k_epi(float* __restrict__ X, const float* __restrict__ X0,
                      const float* __restrict__ G, const float* __restrict__ bias,
                      const float* __restrict__ scaleArr, int layer)
{
    __shared__ float red[8];
    size_t row = blockIdx.x;
    float s = scaleArr[layer];
    int t = threadIdx.x;  // 128
    float4 vv = ((const float4*)(X  + row * DD))[t];
    float4 gg = ((const float4*)(G  + row * DD))[t];
    float4 bb = ((const float4*)(bias))[t];
    float4 v0 = ((const float4*)(X0 + row * DD))[t];
    float4 r4;
    r4.x = 0.8f*(vv.x + s*tanhf(gg.x + bb.x)) + 0.2f*v0.x;
    r4.y = 0.8f*(vv.y + s*tanhf(gg.y + bb.y)) + 0.2f*v0.y;
    r4.z = 0.8f*(vv.z + s*tanhf(gg.z + bb.z)) + 0.2f*v0.z;
    r4.w = 0.8f*(vv.w + s*tanhf(gg.w + bb.w)) + 0.2f*v0.w;
    float ss = r4.x*r4.x + r4.y*r4.y + r4.z*r4.z + r4.w*r4.w;
    ss = blockSum(ss, red);
    float inv = 1.f / fmaxf(sqrtf(ss), 1e-12f);
    r4.x*=inv; r4.y*=inv; r4.z*=inv; r4.w*=inv;
    ((float4*)(X + row * DD))[t] = r4;
}

// VC = l2n(mean_k V_support); Pa = l2n(alpha*P + (1-alpha)*VC)
__global__ void k_vc_pa(const float* __restrict__ V, const float* __restrict__ P,
                        float* __restrict__ Pa, const float* __restrict__ alphaPtr)
{
    __shared__ float red[8];
    int b = blockIdx.x, c = blockIdx.y;
    int t = threadIdx.x;  // 128
    const float* base = V + ((size_t)b * NTOT + (size_t)c * KSHOT) * DD;
    float4 s4 = make_float4(0,0,0,0);
    #pragma unroll
    for (int k = 0; k < KSHOT; k++) {
        float4 x = ((const float4*)(base + (size_t)k * DD))[t];
        s4.x += x.x; s4.y += x.y; s4.z += x.z; s4.w += x.w;
    }
    s4.x *= 0.2f; s4.y *= 0.2f; s4.z *= 0.2f; s4.w *= 0.2f;
    float ss = s4.x*s4.x + s4.y*s4.y + s4.z*s4.z + s4.w*s4.w;
    ss = blockSum(ss, red);
    float inv = 1.f / fmaxf(sqrtf(ss), 1e-12f);
    float a = *alphaPtr;
    float4 p4 = ((const float4*)(P + ((size_t)b * NWAY + c) * DD))[t];
    float4 pa;
    pa.x = a*p4.x + (1.f-a)*s4.x*inv;
    pa.y = a*p4.y + (1.f-a)*s4.y*inv;
    pa.z = a*p4.z + (1.f-a)*s4.z*inv;
    pa.w = a*p4.w + (1.f-a)*s4.w*inv;
    float ss2 = pa.x*pa.x + pa.y*pa.y + pa.z*pa.z + pa.w*pa.w;
    ss2 = blockSum(ss2, red);
    float inv2 = 1.f / fmaxf(sqrtf(ss2), 1e-12f);
    pa.x*=inv2; pa.y*=inv2; pa.z*=inv2; pa.w*=inv2;
    ((float4*)(Pa + ((size_t)b * NWAY + c) * DD))[t] = pa;
}

// cross-modal guidance + per-step logits/CE (+argmax acc on last layer)
__global__ __launch_bounds__(256) void k_guide(
    float* __restrict__ V, const float* __restrict__ Pa,
    const float* __restrict__ betaPtr, const int* __restrict__ qy, int layer)
{
    __shared__ float sPa[NWAY * DD];
    __shared__ float sV[DD];
    __shared__ float sims[NWAY];
    __shared__ float soft[NWAY];
    __shared__ float red[8];
    __shared__ float sInv;
    int b = blockIdx.x, chunk = blockIdx.y;
    int tid = threadIdx.x;
    float beta = *betaPtr;
    const float* PaB = Pa + (size_t)b * NWAY * DD;
    for (int i = tid; i < NWAY * DD; i += 256) sPa[i] = PaB[i];
    __syncthreads();
    int warp = tid >> 5, lane = tid & 31;
    float localLoss = 0.f; int localAcc = 0;
    for (int n = chunk * ROWS_PER_CHUNK; n < chunk * ROWS_PER_CHUNK + ROWS_PER_CHUNK; n++) {
        float* Vrow = V + ((size_t)b * NTOT + n) * DD;
        for (int i = tid; i < DD; i += 256) sV[i] = Vrow[i];
        __syncthreads();
        // 20 dots V . Pa_m
        for (int m = warp; m < NWAY; m += 8) {
            float d = 0.f;
            for (int i = lane; i < DD; i += 32) d += sV[i] * sPa[m * DD + i];
            #pragma unroll
            for (int off = 16; off; off >>= 1) d += __shfl_down_sync(0xffffffffu, d, off);
            if (lane == 0) sims[m] = d;
        }
        __syncthreads();
        if (tid == 0) {
            float mx = -1e30f;
            for (int m = 0; m < NWAY; m++) mx = fmaxf(mx, sims[m]);
            float s = 0.f;
            for (int m = 0; m < NWAY; m++) { float e = expf((sims[m] - mx) * TAUINV); soft[m] = e; s += e; }
            float inv = 1.f / s;
            for (int m = 0; m < NWAY; m++) soft[m] *= inv;
        }
        __syncthreads();
        // guide + residual + norm
        int d0 = tid, d1 = tid + 256;
        float g0 = 0.f, g1 = 0.f;
        #pragma unroll
        for (int m = 0; m < NWAY; m++) {
            g0 += soft[m] * sPa[m * DD + d0];
            g1 += soft[m] * sPa[m * DD + d1];
        }
        float nv0 = beta * sV[d0] + (1.f - beta) * g0;
        float nv1 = beta * sV[d1] + (1.f - beta) * g1;
        float ss = nv0 * nv0 + nv1 * nv1;
        ss = blockSum(ss, red);
        if (tid == 0) sInv = 1.f / fmaxf(sqrtf(ss), 1e-12f);
        __syncthreads();
        nv0 *= sInv; nv1 *= sInv;
        Vrow[d0] = nv0; Vrow[d1] = nv1;
        sV[d0] = nv0; sV[d1] = nv1;
        __syncthreads();
        if (n >= NKQ) {
            for (int m = warp; m < NWAY; m += 8) {
                float d = 0.f;
                for (int i = lane; i < DD; i += 32) d += sV[i] * sPa[m * DD + i];
                #pragma unroll
                for (int off = 16; off; off >>= 1) d += __shfl_down_sync(0xffffffffu, d, off);
                if (lane == 0) sims[m] = 5.0f * d;   // LOGIT_SCALE
            }
            __syncthreads();
            if (tid == 0) {
                float mx = -1e30f; int am = 0;
                for (int m = 0; m < NWAY; m++) if (sims[m] > mx) { mx = sims[m]; am = m; }
                float s = 0.f;
                for (int m = 0; m < NWAY; m++) s += expf(sims[m] - mx);
                float lse = mx + logf(s);
                int lbl = qy[b * QN + (n - NKQ)];
                localLoss += lse - sims[lbl];
                if (layer == LL - 1) localAcc += (am == lbl) ? 1 : 0;
            }
            __syncthreads();
        }
    }
    if (tid == 0) {
        int pi = b * CHUNKS + chunk;
        g_lossP[pi] += localLoss;
        if (layer == LL - 1) g_accP[pi] = localAcc;
    }
}

__global__ void k_final(float* __restrict__ out) {
    __shared__ float red[8];
    int t = threadIdx.x;  // 256
    float ls = 0.f; float ac = 0.f;
    for (int i = t; i < BB * CHUNKS; i += 256) { ls += g_lossP[i]; ac += (float)g_accP[i]; }
    float L = blockSum(ls, red);
    float A = blockSum(ac, red);
    if (t == 0) {
        out[0] = L / (float)(BB * QN * LL);
        out[1] = A / (float)(BB * QN);
    }
}

// ---------------- launch ----------------
extern "C" void kernel_launch(void* const* d_in, const int* in_sizes, int n_in,
                              void* d_out, int out_size)
{
    const float* V_feat = (const float*)d_in[0];
    const float* P_feat = (const float*)d_in[1];
    const int*   qy     = (const int*)  d_in[2];
    const float* igbW   = (const float*)d_in[3];
    const float* igbB   = (const float*)d_in[4];
    const float* igbS   = (const float*)d_in[5];
    const float* pgbW   = (const float*)d_in[6];
    const float* pgbB   = (const float*)d_in[7];
    const float* pgbS   = (const float*)d_in[8];
    const float* alpha  = (const float*)d_in[9];
    const float* beta   = (const float*)d_in[10];
    float* out = (float*)d_out;

    float *pV, *pV0, *pMsg, *pGemm, *pP, *pP0, *pPmsg, *pPgemm, *pPa, *pSim, *pSimP, *pW, *pWP;
    int *pIdx, *pIdxP;
    cudaGetSymbolAddress((void**)&pV,    g_V);
    cudaGetSymbolAddress((void**)&pV0,   g_V0);
    cudaGetSymbolAddress((void**)&pMsg,  g_msg);
    cudaGetSymbolAddress((void**)&pGemm, g_gemm);
    cudaGetSymbolAddress((void**)&pP,    g_P);
    cudaGetSymbolAddress((void**)&pP0,   g_P0);
    cudaGetSymbolAddress((void**)&pPmsg, g_Pmsg);
    cudaGetSymbolAddress((void**)&pPgemm,g_Pgemm);
    cudaGetSymbolAddress((void**)&pPa,   g_Pa);
    cudaGetSymbolAddress((void**)&pSim,  g_sim);
    cudaGetSymbolAddress((void**)&pSimP, g_simP);
    cudaGetSymbolAddress((void**)&pW,    g_w);
    cudaGetSymbolAddress((void**)&pWP,   g_wP);
    cudaGetSymbolAddress((void**)&pIdx,  g_idx);
    cudaGetSymbolAddress((void**)&pIdxP, g_idxP);

    k_zero<<<(BB * CHUNKS + 255) / 256, 256>>>();
    k_init<<<BB * NTOT, 128>>>(V_feat, pV, pV0);
    k_init<<<BB * NWAY, 128>>>(P_feat, pP, pP0);

    for (int i = 0; i < LL; i++) {
        // ---- instance branch ----
        {
            dim3 gs((NTOT + 127) / 128, (NTOT + 127) / 128, BB);
            k_gemm_nt<<<gs, 256>>>(pV, pV, pSim, NTOT, NTOT, DD,
                                   (size_t)NTOT * DD, (size_t)NTOT * DD, (size_t)NTOT * NTOT);
        }
        k_topk<<<(BB * NTOT + 3) / 4, 128>>>(pSim, NTOT, BB * NTOT, pIdx, pW);
        k_gather<<<BB * NTOT, 128>>>(pV, pIdx, pW, pMsg, NTOT);
        {
            dim3 gs((DD + 127) / 128, (BB * NTOT + 127) / 128, 1);
            k_gemm_nt<<<gs, 256>>>(pMsg, igbW + (size_t)i * DD * DD, pGemm,
                                   BB * NTOT, DD, DD, 0, 0, 0);
        }
        k_epi<<<BB * NTOT, 128>>>(pV, pV0, pGemm, igbB + (size_t)i * DD, igbS, i);
        // ---- prototype branch ----
        {
            dim3 gs(1, 1, BB);
            k_gemm_nt<<<gs, 256>>>(pP, pP, pSimP, NWAY, NWAY, DD,
                                   (size_t)NWAY * DD, (size_t)NWAY * DD, (size_t)NWAY * NWAY);
        }
        k_topk<<<(BB * NWAY + 3) / 4, 128>>>(pSimP, NWAY, BB * NWAY, pIdxP, pWP);
        k_gather<<<BB * NWAY, 128>>>(pP, pIdxP, pWP, pPmsg, NWAY);
        {
            dim3 gs((DD + 127) / 128, (BB * NWAY + 127) / 128, 1);
            k_gemm_nt<<<gs, 256>>>(pPmsg, pgbW + (size_t)i * DD * DD, pPgemm,
                                   BB * NWAY, DD, DD, 0, 0, 0);
        }
        k_epi<<<BB * NWAY, 128>>>(pP, pP0, pPgemm, pgbB + (size_t)i * DD, pgbS, i);
        // ---- centers, adapted prototypes, guidance + logits/CE ----
        k_vc_pa<<<dim3(BB, NWAY), 128>>>(pV, pP, pPa, alpha);
        k_guide<<<dim3(BB, CHUNKS), 256>>>(pV, pPa, beta, qy, i);
    }
    k_final<<<1, 256>>>(out);
}